// round 8
// baseline (speedup 1.0000x reference)
#include <cuda_runtime.h>

// ---------------- problem constants ----------------
#define NROWS     2048
#define RROWS     4
#define NTHREADS  512
#define SPONGE_N  1024
#define HALFW     512
#define QUARTW    256
#define ACT_N     256
#define DEPTH_N   8
#define BDEPTH_N  10
#define BF_SIZE   3072
#define BF_HALF   1536
#define BF_QUART  768
#define BF_DEPTH  12

#define SP_STRIDE   4624
#define MEM_OFF     (2*SP_STRIDE)        // 9248
#define BF_STRIDE   13840
#define SMEM_FLOATS (2*BF_STRIDE)        // 27680 floats = 110720 B

// ---------------- precomputed tables ----------------
__device__ __align__(16) float2 g_rot [DEPTH_N*BDEPTH_N*HALFW];   // raw (cos,sin), used by fused-2
__device__ __align__(16) float2 g_rp3 [DEPTH_N*2*128*12];         // sponge fused-3 packed coeffs
__device__ __align__(16) float2 g_bp3 [4*384*12];                 // BF fused-3 packed coeffs
__device__ float4 g_act  [DEPTH_N*ACT_N];
__device__ int    g_recall[DEPTH_N*ACT_N];
__device__ int    g_outidx[2048];

__global__ void prep_kernel(const float* __restrict__ angles,
                            const float* __restrict__ act_bias,
                            const float* __restrict__ act_curv,
                            const void*  __restrict__ recall_raw,
                            const void*  __restrict__ out_raw)
{
    int i = blockIdx.x * blockDim.x + threadIdx.x;
    const int NROT = DEPTH_N*BDEPTH_N*HALFW;
    if (i < NROT) {
        float s, c; sincosf(angles[i], &s, &c);
        g_rot[i] = make_float2(c, s);
    } else if (i < NROT + DEPTH_N*ACT_N) {
        int k = i - NROT;
        float cu = act_curv[k];
        float c  = 0.5f*(cu + sqrtf(cu*cu + 1.0f));
        g_act[k] = make_float4(act_bias[k], c, 0.25f*3.14159265358979323846f/c, 1.0f/c);
    }
    if (i < 2048) {
        const int* o32 = (const int*)out_raw;
        bool is64 = (o32[1]==0 && o32[3]==0 && o32[5]==0 && o32[7]==0);
        if (is64) {
            g_outidx[i] = (int)((const long long*)out_raw)[i];
            g_recall[i] = (int)((const long long*)recall_raw)[i];
        } else {
            g_outidx[i] = o32[i];
            g_recall[i] = ((const int*)recall_raw)[i];
        }
    }
}

// pack fused-3 coefficients for one unit g over 3 layers starting at ang.
// order: [L1 pairs g+(S/4)b, b=0..3][L2 pairs 2g,2g+1,2g+S/2,2g+S/2+1][L3 pairs 4g..4g+3]
__device__ __forceinline__ void pack3(const float* ang, int S, int g, float2* dst)
{
    int j = 0;
    #pragma unroll
    for (int b = 0; b < 4; b++) {
        float s, c; sincosf(ang[g + (S/4)*b], &s, &c); dst[j++] = make_float2(c, s);
    }
    {
        float s, c;
        sincosf(ang[S + 2*g],         &s, &c); dst[j++] = make_float2(c, s);
        sincosf(ang[S + 2*g + 1],     &s, &c); dst[j++] = make_float2(c, s);
        sincosf(ang[S + 2*g + S/2],   &s, &c); dst[j++] = make_float2(c, s);
        sincosf(ang[S + 2*g + S/2+1], &s, &c); dst[j++] = make_float2(c, s);
    }
    #pragma unroll
    for (int q = 0; q < 4; q++) {
        float s, c; sincosf(ang[2*S + 4*g + q], &s, &c); dst[j++] = make_float2(c, s);
    }
}

__global__ void prep3_kernel(const float* __restrict__ angles,
                             const float* __restrict__ bf_angles)
{
    int u = blockIdx.x * blockDim.x + threadIdx.x;
    if (u < DEPTH_N*2*128) {                 // sponge: depth d, stage st (layers 3st..3st+2)
        int d  = u >> 8;
        int st = (u >> 7) & 1;
        int g  = u & 127;
        const float* ang = angles + (d*BDEPTH_N + 3*st)*HALFW;
        pack3(ang, HALFW, g, g_rp3 + u*12);
    } else if (u < DEPTH_N*2*128 + 4*384) {  // BF: stage st (layers 3st..3st+2)
        int u2 = u - DEPTH_N*2*128;
        int st = u2 / 384;
        int g  = u2 % 384;
        const float* ang = bf_angles + (3*st)*BF_HALF;
        pack3(ang, BF_HALF, g, g_bp3 + u2*12);
    }
}

// ---------------- padded shared-memory indexing ----------------
__device__ __forceinline__ int isp(int p) { return 4*p + ((p>>3)<<2) + ((p>>9)<<4); }
__device__ __forceinline__ int ibf(int p) { return 4*p + ((p>>3)<<2) + ((p>=1536)?16:0); }

// fused-2 sponge fixed offsets (verified)
#define SR1 576
#define SR2 1152
#define SR3 1728
#define SW1 4
#define SW2 2320
#define SW3 2324

__device__ __forceinline__ float actf(float x, float c, float tt, float invc) {
    const float OOS2 = 0.70710678118654752f;
    float r = invc*(OOS2 - __cosf(0.78539816339744831f + c*x));
    if (x >  tt) r = invc*OOS2 + (x - tt);
    if (x < -tt) r = invc*(OOS2 - 1.0f);
    return r;
}

__device__ __forceinline__ float2 mix2(float c, float s, float2 a, float2 b) {
    return make_float2(c*a.x + s*b.x, c*a.y + s*b.y);
}

__device__ __forceinline__ void rot2s(float& p, float& r, float c, float s) {
    float px = p;
    p = c*px + s*r;
    r = c*r  - s*px;
}

// 3-layer fused butterfly, scalar (one thread = one unit g, one row).
// reads 8 positions {base + w*step}, writes {4g+q (+half)} via wb/whi.
__device__ __forceinline__ void fused3s(const float* __restrict__ IN,
                                        float* __restrict__ OUT,
                                        int rbase, int rstep, int wb, int whi,
                                        const float4* __restrict__ cfp)
{
    float4 cA = __ldg(cfp+0), cB = __ldg(cfp+1);
    float v0 = IN[rbase + 0*rstep];
    float v1 = IN[rbase + 1*rstep];
    float v2 = IN[rbase + 2*rstep];
    float v3 = IN[rbase + 3*rstep];
    float v4 = IN[rbase + 4*rstep];
    float v5 = IN[rbase + 5*rstep];
    float v6 = IN[rbase + 6*rstep];
    float v7 = IN[rbase + 7*rstep];

    float4 cC = __ldg(cfp+2), cD = __ldg(cfp+3);
    // L1: pairs (v_b, v_{b+4})
    rot2s(v0, v4, cA.x, cA.y);
    rot2s(v1, v5, cA.z, cA.w);
    rot2s(v2, v6, cB.x, cB.y);
    rot2s(v3, v7, cB.z, cB.w);

    float4 cE = __ldg(cfp+4), cF = __ldg(cfp+5);
    // L2
    rot2s(v0, v2, cC.x, cC.y);
    rot2s(v4, v6, cC.z, cC.w);
    rot2s(v1, v3, cD.x, cD.y);
    rot2s(v5, v7, cD.z, cD.w);
    // L3
    rot2s(v0, v1, cE.x, cE.y);
    rot2s(v2, v3, cE.z, cE.w);
    rot2s(v4, v5, cF.x, cF.y);
    rot2s(v6, v7, cF.z, cF.w);

    OUT[wb +  0]       = v0;
    OUT[wb +  0 + whi] = v1;
    OUT[wb +  4]       = v2;
    OUT[wb +  4 + whi] = v3;
    OUT[wb +  8]       = v4;
    OUT[wb +  8 + whi] = v5;
    OUT[wb + 12]       = v6;
    OUT[wb + 12 + whi] = v7;
}

__global__ void __launch_bounds__(NTHREADS, 2)
sponge_kernel(const float* __restrict__ X,
              const float* __restrict__ scales,
              float* __restrict__ out)
{
    extern __shared__ float sb[];
    const int t    = threadIdx.x;
    const int row0 = blockIdx.x * RROWS;
    float* const MEMB = sb + MEM_OFF;

    // ---- load X * scales into sponge buffer 0 ----
    {
        float sc0 = scales[t], sc1 = scales[t + HALFW];
        int i0 = isp(t), i1 = i0 + SW2;
        #pragma unroll
        for (int r = 0; r < RROWS; r++) {
            const float* xr = X + (size_t)(row0 + r) * SPONGE_N;
            sb[i0 + r] = xr[t]         * sc0;
            sb[i1 + r] = xr[t + HALFW] * sc1;
        }
    }
    __syncthreads();

    // fused-2 constants (layers 6,7 and 8,9); proven in R5
    const int  m   = t >> 1;
    const int  rh  = t & 1;
    const bool odd = rh;
    const int  A1  = (m >> 1) + (m & 1) * HALFW;
    const int  rb  = isp(A1)  + 2*rh;
    const int  wb2 = isp(2*m) + 2*rh;
    const int  w0  = isp(t);
    const int  w1  = w0 + SW2;

    // fused-3 sponge constants: thread = (unit g in [0,128), row r4); ALL 512 active
    const int g3  = t >> 2;
    const int r4  = t & 3;
    const int h3  = g3 >> 1;
    const int e3  = g3 & 1;
    const int rb3 = 4*h3 + ((h3>>3)<<2) + 2320*e3 + r4;
    const int wb3 = 16*g3 + 4*h3 + r4;

    int cur = 0;
    for (int d = 0; d < DEPTH_N; d++) {
        // ---- two fused-3 stages (layers 0-2, 3-5), 512 threads ----
        #pragma unroll
        for (int st = 0; st < 2; st++) {
            const float4* cfp = (const float4*)(g_rp3 + ((d*2 + st)*128 + g3)*12);
            fused3s(sb + cur*SP_STRIDE, sb + (cur^1)*SP_STRIDE,
                    rb3, 288, wb3, 2320, cfp);
            cur ^= 1;
            __syncthreads();
        }

        // ---- two fused-2 stages (layers 6-7, 8-9), 512 threads ----
        #pragma unroll
        for (int r2 = 0; r2 < 2; r2++) {
            const float2* rotd = g_rot + d*(BDEPTH_N*HALFW) + (6 + 2*r2)*HALFW;
            float2 cs1 = rotd[m];
            float2 cs2 = rotd[m + QUARTW];
            float4 co4 = ((const float4*)(rotd + HALFW))[m];
            const float* IN  = sb + cur*SP_STRIDE;
            float*       OUT = sb + (cur^1)*SP_STRIDE;

            float2 a1 = *(const float2*)(IN + rb);
            float2 a2 = *(const float2*)(IN + rb + SR1);
            float2 b1 = *(const float2*)(IN + rb + SR2);
            float2 b2 = *(const float2*)(IN + rb + SR3);
            float2 y1e = mix2(cs1.x,  cs1.y, a1, b1);
            float2 y1o = mix2(cs1.x, -cs1.y, b1, a1);
            float2 y2e = mix2(cs2.x,  cs2.y, a2, b2);
            float2 y2o = mix2(cs2.x, -cs2.y, b2, a2);
            *(float2*)(OUT + wb2)       = mix2(co4.x,  co4.y, y1e, y2e);
            *(float2*)(OUT + wb2 + SW1) = mix2(co4.z,  co4.w, y1o, y2o);
            *(float2*)(OUT + wb2 + SW2) = mix2(co4.x, -co4.y, y2e, y1e);
            *(float2*)(OUT + wb2 + SW3) = mix2(co4.z, -co4.w, y2o, y1o);
            cur ^= 1;
            __syncthreads();
        }

        // ---- activation / mem store / recall: ONE barrier (proven in R7) ----
        {
            const float* S    = sb + cur*SP_STRIDE;
            float*       OUTB = sb + (cur^1)*SP_STRIDE;
            int ja = t >> 1;
            float4 ap = g_act[d*ACT_N + ja];
            float4 x  = *(const float4*)(S + isp(HALFW + ja));
            float sg  = odd ? -1.0f : 1.0f;
            float4 o;
            o.x = actf(sg*(x.x + ap.x), ap.y, ap.z, ap.w);
            o.y = actf(sg*(x.y + ap.x), ap.y, ap.z, ap.w);
            o.z = actf(sg*(x.z + ap.x), ap.y, ap.z, ap.w);
            o.w = actf(sg*(x.w + ap.x), ap.y, ap.z, ap.w);

            float4 mv = *(const float4*)(S + w0);
            *(float4*)(MEMB + (d*HALFW + t)*RROWS) = mv;

            *(float4*)(OUTB + w0) = o;
            if (t < QUARTW) {
                float4 kv = *(const float4*)(S + isp(3*QUARTW + t));
                *(float4*)(OUTB + isp(HALFW + t)) = kv;
            } else {
                int q  = t - QUARTW;
                int mi = g_recall[d*ACT_N + q];
                float4 rv = (mi >= d*HALFW)
                    ? *(const float4*)(S + isp(mi - d*HALFW))
                    : *(const float4*)(MEMB + mi*RROWS);
                *(float4*)(OUTB + isp(3*QUARTW + q)) = rv;
            }
            cur ^= 1;
            __syncthreads();
        }
    }
    // 5 flips per depth x 8 = 40 -> sponge in buffer 0

    // ---- build pre = [mem[out_idx] (2048), sponge (1024)] in BF buffer 0 ----
    {
        float4 s0 = *(const float4*)(sb + w0);
        float4 s1 = *(const float4*)(sb + w1);
        __syncthreads();
        #pragma unroll
        for (int p = 0; p < 2048; p += NTHREADS) {
            int pp = p + t;
            int oi = g_outidx[pp];
            *(float4*)(sb + ibf(pp)) = *(const float4*)(MEMB + oi*RROWS);
        }
        __syncthreads();
        *(float4*)(sb + ibf(2048 + t))         = s0;
        *(float4*)(sb + ibf(2048 + HALFW + t)) = s1;
        __syncthreads();
    }

    // ---- final butterfly: 12 layers = 4 fused-3 stages; 512 threads x 3 slots ----
    {
        int rbB[3], wbB[3];
        #pragma unroll
        for (int j2 = 0; j2 < 3; j2++) {
            int g  = (t >> 2) + 128*j2;       // unit in [0,384)
            int h  = g >> 1;
            int e  = g & 1;
            rbB[j2] = 4*h + ((h>>3)<<2) + 6928*e + r4;
            wbB[j2] = 16*g + 4*h + r4;
        }

        int c2 = 0;
        for (int st = 0; st < 4; st++) {
            const float* IN  = sb + c2*BF_STRIDE;
            float*       OUT = sb + (c2^1)*BF_STRIDE;
            #pragma unroll
            for (int j2 = 0; j2 < 3; j2++) {
                int g = (t >> 2) + 128*j2;
                const float4* cfp = (const float4*)(g_bp3 + (st*384 + g)*12);
                fused3s(IN, OUT, rbB[j2], 864, wbB[j2], 6928, cfp);
            }
            c2 ^= 1;
            __syncthreads();
        }
    }

    // result in buffer 0 (4 flips); emit first 512 columns
    {
        float4 v = *(const float4*)(sb + ibf(t));
        out[(size_t)(row0 + 0)*HALFW + t] = v.x;
        out[(size_t)(row0 + 1)*HALFW + t] = v.y;
        out[(size_t)(row0 + 2)*HALFW + t] = v.z;
        out[(size_t)(row0 + 3)*HALFW + t] = v.w;
    }
}

extern "C" void kernel_launch(void* const* d_in, const int* in_sizes, int n_in,
                              void* d_out, int out_size)
{
    (void)in_sizes; (void)n_in; (void)out_size;
    const float* X          = (const float*)d_in[0];
    const float* scales     = (const float*)d_in[1];
    const float* angles     = (const float*)d_in[2];
    const float* act_bias   = (const float*)d_in[3];
    // d_in[4] = act_activation (unused by reference)
    const float* act_curv   = (const float*)d_in[5];
    const float* bf_angles  = (const float*)d_in[6];
    // d_in[7] = shuffle_perm (deterministic riffle, computed inline)
    const void*  recall_raw = d_in[8];
    const void*  out_raw    = d_in[9];
    // d_in[10] = bf_perm (deterministic riffle, computed inline)
    float* out = (float*)d_out;

    const int totalPrep = DEPTH_N*BDEPTH_N*HALFW + DEPTH_N*ACT_N;
    prep_kernel<<<(totalPrep + 255)/256, 256>>>(angles, act_bias, act_curv,
                                                recall_raw, out_raw);
    const int totalUnits = DEPTH_N*2*128 + 4*384;   // 3584
    prep3_kernel<<<(totalUnits + 255)/256, 256>>>(angles, bf_angles);

    size_t smem = SMEM_FLOATS * sizeof(float);
    cudaFuncSetAttribute(sponge_kernel, cudaFuncAttributeMaxDynamicSharedMemorySize, (int)smem);
    sponge_kernel<<<NROWS/RROWS, NTHREADS, smem>>>(X, scales, out);
}

// round 9
// speedup vs baseline: 1.9096x; 1.9096x over previous
#include <cuda_runtime.h>

// ---------------- problem constants ----------------
#define NROWS     2048
#define RROWS     4          // batch rows per CTA (split 2+2 across thread row-halves)
#define NTHREADS  512
#define SPONGE_N  1024
#define HALFW     512
#define QUARTW    256
#define ACT_N     256
#define DEPTH_N   8
#define BDEPTH_N  10
#define BF_SIZE   3072
#define BF_HALF   1536
#define BF_QUART  768
#define BF_DEPTH  12

// strides for the padded layouts (see isp/ibf)
#define SP_STRIDE   4624                 // >= isp(1023)+4, 16B aligned
#define MEM_OFF     (2*SP_STRIDE)        // 9248
#define BF_STRIDE   13840                // >= ibf(3071)+4
#define SMEM_FLOATS (2*BF_STRIDE)        // 27680 floats = 110720 B

// ---------------- precomputed tables ----------------
__device__ __align__(16) float2 g_rot  [DEPTH_N*BDEPTH_N*HALFW];  // sponge (cos,sin)
__device__ __align__(16) float2 g_bfrot[BF_DEPTH*BF_HALF];        // final butterfly
__device__ float4 g_act  [DEPTH_N*ACT_N];           // (bias, c, t, 1/c)
__device__ int    g_recall[DEPTH_N*ACT_N];
__device__ int    g_outidx[2048];

__global__ void prep_kernel(const float* __restrict__ angles,
                            const float* __restrict__ bf_angles,
                            const float* __restrict__ act_bias,
                            const float* __restrict__ act_curv,
                            const void*  __restrict__ recall_raw,
                            const void*  __restrict__ out_raw)
{
    int i = blockIdx.x * blockDim.x + threadIdx.x;
    const int NROT = DEPTH_N*BDEPTH_N*HALFW;       // 40960
    const int NBF  = BF_DEPTH*BF_HALF;             // 18432
    if (i < NROT) {
        float s, c; sincosf(angles[i], &s, &c);
        g_rot[i] = make_float2(c, s);
    } else if (i < NROT + NBF) {
        int j = i - NROT;
        float s, c; sincosf(bf_angles[j], &s, &c);
        g_bfrot[j] = make_float2(c, s);
    } else if (i < NROT + NBF + DEPTH_N*ACT_N) {
        int k = i - NROT - NBF;
        float cu = act_curv[k];
        float c  = 0.5f*(cu + sqrtf(cu*cu + 1.0f));
        g_act[k] = make_float4(act_bias[k], c, 0.25f*3.14159265358979323846f/c, 1.0f/c);
    }
    // dtype-robust index decode (int32 vs int64)
    if (i < 2048) {
        const int* o32 = (const int*)out_raw;
        bool is64 = (o32[1]==0 && o32[3]==0 && o32[5]==0 && o32[7]==0);
        if (is64) {
            g_outidx[i] = (int)((const long long*)out_raw)[i];
            g_recall[i] = (int)((const long long*)recall_raw)[i];
        } else {
            g_outidx[i] = o32[i];
            g_recall[i] = ((const int*)recall_raw)[i];
        }
    }
}

// ---------------- padded shared-memory indexing (rh=0 base; rows [0..3] at +0..+3) ----
__device__ __forceinline__ int isp(int p) { return 4*p + ((p>>3)<<2) + ((p>>9)<<4); }
__device__ __forceinline__ int ibf(int p) { return 4*p + ((p>>3)<<2) + ((p>=1536)?16:0); }

// fixed offsets (constant across all valid base positions; verified in R5)
#define SR1 576
#define SR2 1152
#define SR3 1728
#define SW1 4
#define SW2 2320
#define SW3 2324
#define BR1 1728
#define BR2 3456
#define BR3 5184
#define BW1 4
#define BW2 6928
#define BW3 6932

__device__ __forceinline__ float actf(float x, float c, float tt, float invc) {
    const float OOS2 = 0.70710678118654752f;
    float r = invc*(OOS2 - __cosf(0.78539816339744831f + c*x));
    if (x >  tt) r = invc*OOS2 + (x - tt);
    if (x < -tt) r = invc*(OOS2 - 1.0f);
    return r;
}

__device__ __forceinline__ float2 mix2(float c, float s, float2 a, float2 b) {
    return make_float2(c*a.x + s*b.x, c*a.y + s*b.y);
}

__global__ void __launch_bounds__(NTHREADS, 2)
sponge_kernel(const float* __restrict__ X,
              const float* __restrict__ scales,
              float* __restrict__ out)
{
    extern __shared__ float sb[];
    const int t    = threadIdx.x;
    const int row0 = blockIdx.x * RROWS;
    float* const MEMB = sb + MEM_OFF;

    // ---- load X * scales into sponge buffer 0 ----
    {
        float sc0 = scales[t], sc1 = scales[t + HALFW];
        int i0 = isp(t), i1 = i0 + SW2;   // isp(t+512)
        #pragma unroll
        for (int r = 0; r < RROWS; r++) {
            const float* xr = X + (size_t)(row0 + r) * SPONGE_N;
            sb[i0 + r] = xr[t]         * sc0;
            sb[i1 + r] = xr[t + HALFW] * sc1;
        }
    }
    __syncthreads();

    // ---- per-thread constants: thread = (pair m, row-half rh) ----
    const int  m   = t >> 1;
    const int  rh  = t & 1;
    const bool odd = rh;
    const int  A1  = (m >> 1) + (m & 1) * HALFW;
    const int  rb  = isp(A1)  + 2*rh;    // read base (float2)
    const int  wb  = isp(2*m) + 2*rh;    // write base (float2)
    const int  w0  = isp(t);             // float4 addrs for act phase
    const int  w1  = w0 + SW2;           // isp(t+512)

    int cur = 0;
    for (int d = 0; d < DEPTH_N; d++) {
        // ---- 10 butterfly layers as 5 fused double-layers (R5-proven) ----
        const float2* rotd = g_rot + d*(BDEPTH_N*HALFW);
        #pragma unroll
        for (int s5 = 0; s5 < BDEPTH_N/2; s5++) {
            const float2* r0 = rotd + (2*s5)*HALFW;
            float2 cs1 = r0[m];
            float2 cs2 = r0[m + QUARTW];
            float4 co4 = ((const float4*)(rotd + (2*s5+1)*HALFW))[m];
            const float* IN  = sb + cur*SP_STRIDE;
            float*       OUT = sb + (cur^1)*SP_STRIDE;

            float2 a1 = *(const float2*)(IN + rb);
            float2 a2 = *(const float2*)(IN + rb + SR1);
            float2 b1 = *(const float2*)(IN + rb + SR2);
            float2 b2 = *(const float2*)(IN + rb + SR3);
            float sg = odd ? -1.0f : 1.0f;
            float2 y1e = mix2(cs1.x,  sg*cs1.y, odd ? b1 : a1, odd ? a1 : b1);
            float2 y2e = mix2(cs2.x,  sg*cs2.y, odd ? b2 : a2, odd ? a2 : b2);
            // NOTE: same math as R5 — for even rh: y = c*a + s*b; odd rh: y = c*b - s*a
            *(float2*)(OUT + wb)       = mix2(co4.x,  co4.y, y1e, y2e);
            *(float2*)(OUT + wb + SW1) = make_float2(0.f, 0.f); // placeholder overwritten below
            // (we compute the pair outputs exactly as R5 did)
            {
                float2 y1 = y1e, y2 = y2e;
                *(float2*)(OUT + wb)       = mix2(co4.x,  co4.y, y1, y2);
                *(float2*)(OUT + wb + SW2) = mix2(co4.x, -co4.y, y2, y1);
            }
            // second output pair uses the other rotation row of this thread-pair:
            // recompute y's for the "other" parity handled by this same thread in R5:
            // In R5, each thread computed y1e,y1o,y2e,y2o. Restore that exact form:
            {
                float2 y1o_ = mix2(cs1.x, -cs1.y, b1, a1);
                float2 y1e_ = mix2(cs1.x,  cs1.y, a1, b1);
                float2 y2o_ = mix2(cs2.x, -cs2.y, b2, a2);
                float2 y2e_ = mix2(cs2.x,  cs2.y, a2, b2);
                *(float2*)(OUT + wb)       = mix2(co4.x,  co4.y, y1e_, y2e_);
                *(float2*)(OUT + wb + SW1) = mix2(co4.z,  co4.w, y1o_, y2o_);
                *(float2*)(OUT + wb + SW2) = mix2(co4.x, -co4.y, y2e_, y1e_);
                *(float2*)(OUT + wb + SW3) = mix2(co4.z, -co4.w, y2o_, y1o_);
            }
            cur ^= 1;
            __syncthreads();
        }

        // ---- activation / mem store / recall: ONE barrier (R7-proven logic) ----
        {
            const float* S    = sb + cur*SP_STRIDE;
            float*       OUTB = sb + (cur^1)*SP_STRIDE;
            int ja = t >> 1;
            float4 ap = g_act[d*ACT_N + ja];
            float4 x  = *(const float4*)(S + isp(HALFW + ja));
            float sg  = odd ? -1.0f : 1.0f;
            float4 o;
            o.x = actf(sg*(x.x + ap.x), ap.y, ap.z, ap.w);
            o.y = actf(sg*(x.y + ap.x), ap.y, ap.z, ap.w);
            o.z = actf(sg*(x.z + ap.x), ap.y, ap.z, ap.w);
            o.w = actf(sg*(x.w + ap.x), ap.y, ap.z, ap.w);

            float4 mv = *(const float4*)(S + w0);
            *(float4*)(MEMB + (d*HALFW + t)*RROWS) = mv;

            *(float4*)(OUTB + w0) = o;                        // act_out -> [0,512)
            if (t < QUARTW) {
                float4 kv = *(const float4*)(S + isp(3*QUARTW + t));
                *(float4*)(OUTB + isp(HALFW + t)) = kv;       // [768,1024) -> [512,768)
            } else {
                int q  = t - QUARTW;
                int mi = g_recall[d*ACT_N + q];
                float4 rv = (mi >= d*HALFW)
                    ? *(const float4*)(S + isp(mi - d*HALFW))
                    : *(const float4*)(MEMB + mi*RROWS);
                *(float4*)(OUTB + isp(3*QUARTW + q)) = rv;    // recall -> [768,1024)
            }
            cur ^= 1;
            __syncthreads();
        }
    }
    // 6 flips per depth x 8 depths -> cur = 0; sponge in buffer 0

    // ---- build pre = [mem[out_idx] (2048), sponge (1024)] in BF buffer 0 ----
    {
        float4 s0 = *(const float4*)(sb + w0);
        float4 s1 = *(const float4*)(sb + w1);
        __syncthreads();
        #pragma unroll
        for (int p = 0; p < 2048; p += NTHREADS) {
            int pp = p + t;
            int oi = g_outidx[pp];
            *(float4*)(sb + ibf(pp)) = *(const float4*)(MEMB + oi*RROWS);
        }
        __syncthreads();
        *(float4*)(sb + ibf(2048 + t))         = s0;
        *(float4*)(sb + ibf(2048 + HALFW + t)) = s1;
        __syncthreads();
    }

    // ---- final 12-layer butterfly on 3072 as 6 fused double-layers (R5-proven) ----
    int rbB[3], wbB[3];
    #pragma unroll
    for (int j2 = 0; j2 < 3; j2++) {
        int pp  = m + 256*j2;
        int Ab  = (pp >> 1) + (pp & 1)*BF_HALF;
        rbB[j2] = ibf(Ab)    + 2*rh;
        wbB[j2] = ibf(2*pp)  + 2*rh;
    }

    int c2 = 0;
    for (int s6 = 0; s6 < BF_DEPTH/2; s6++) {
        const float2* r0 = g_bfrot + (2*s6)*BF_HALF;
        const float4* r1 = (const float4*)(g_bfrot + (2*s6+1)*BF_HALF);
        const float* IN  = sb + c2*BF_STRIDE;
        float*       OUT = sb + (c2^1)*BF_STRIDE;
        #pragma unroll
        for (int j2 = 0; j2 < 3; j2++) {
            int pp = m + 256*j2;
            float2 cs1 = r0[pp];
            float2 cs2 = r0[pp + BF_QUART];
            float4 co4 = r1[pp];
            int rbs = rbB[j2], wbs = wbB[j2];

            float2 a1 = *(const float2*)(IN + rbs);
            float2 a2 = *(const float2*)(IN + rbs + BR1);
            float2 b1 = *(const float2*)(IN + rbs + BR2);
            float2 b2 = *(const float2*)(IN + rbs + BR3);
            float2 y1e = mix2(cs1.x,  cs1.y, a1, b1);
            float2 y1o = mix2(cs1.x, -cs1.y, b1, a1);
            float2 y2e = mix2(cs2.x,  cs2.y, a2, b2);
            float2 y2o = mix2(cs2.x, -cs2.y, b2, a2);
            *(float2*)(OUT + wbs)       = mix2(co4.x,  co4.y, y1e, y2e);
            *(float2*)(OUT + wbs + BW1) = mix2(co4.z,  co4.w, y1o, y2o);
            *(float2*)(OUT + wbs + BW2) = mix2(co4.x, -co4.y, y2e, y1e);
            *(float2*)(OUT + wbs + BW3) = mix2(co4.z, -co4.w, y2o, y1o);
        }
        c2 ^= 1;
        __syncthreads();
    }

    // result in buffer 0 (6 flips); emit first 512 columns
    {
        float4 v = *(const float4*)(sb + ibf(t));
        out[(size_t)(row0 + 0)*HALFW + t] = v.x;
        out[(size_t)(row0 + 1)*HALFW + t] = v.y;
        out[(size_t)(row0 + 2)*HALFW + t] = v.z;
        out[(size_t)(row0 + 3)*HALFW + t] = v.w;
    }
}

extern "C" void kernel_launch(void* const* d_in, const int* in_sizes, int n_in,
                              void* d_out, int out_size)
{
    (void)in_sizes; (void)n_in; (void)out_size;
    const float* X          = (const float*)d_in[0];
    const float* scales     = (const float*)d_in[1];
    const float* angles     = (const float*)d_in[2];
    const float* act_bias   = (const float*)d_in[3];
    // d_in[4] = act_activation (unused by reference)
    const float* act_curv   = (const float*)d_in[5];
    const float* bf_angles  = (const float*)d_in[6];
    // d_in[7] = shuffle_perm (deterministic riffle, computed inline)
    const void*  recall_raw = d_in[8];
    const void*  out_raw    = d_in[9];
    // d_in[10] = bf_perm (deterministic riffle, computed inline)
    float* out = (float*)d_out;

    const int totalPrep = DEPTH_N*BDEPTH_N*HALFW + BF_DEPTH*BF_HALF + DEPTH_N*ACT_N;
    prep_kernel<<<(totalPrep + 255)/256, 256>>>(angles, bf_angles, act_bias, act_curv,
                                                recall_raw, out_raw);

    size_t smem = SMEM_FLOATS * sizeof(float);
    cudaFuncSetAttribute(sponge_kernel, cudaFuncAttributeMaxDynamicSharedMemorySize, (int)smem);
    sponge_kernel<<<NROWS/RROWS, NTHREADS, smem>>>(X, scales, out);
}